// round 15
// baseline (speedup 1.0000x reference)
#include <cuda_runtime.h>
#include <cuda_bf16.h>
#include <stdint.h>

// ---------------------------------------------------------------------------
// Hodge1LapEdgeEncoder
//
// Output (float32): [0,P) idx rows | [P,2P) idx cols | [2P,2P+P*D) dense vals
//   dense[slot,:] = padding + sum_{e: slot(e)==slot} (edge_attr[e] + pestat[e,0]*fc_w)
//   slot(e) = u*n + (v%n),  u = ei[0,e], v = ei[1,e]
//   Edges of graph g occupy the contiguous range [g*epg, (g+1)*epg).
//
// Tier 1: two-stream chunked pipeline inside the captured graph.
//   origin stream: init chunk 0..3 (padding broadcast, write-bound)
//   side stream  : (after fork event!) idx pattern, then scatter chunk i
//                  gated on evInit[i] -> overlaps init chunk i+1.
// Tier 2: proven serial path (init4 + idx/scatter, 20.4us).
// Tier 3: generic scalar path.
// ---------------------------------------------------------------------------

#define TB 256
#define IPT 4            // float4 stores per init thread
#define NCHUNK 4

__device__ __forceinline__ void red_add_v4(float* dst, float4 r)
{
#if __CUDA_ARCH__ >= 900
    asm volatile("red.global.add.v4.f32 [%0], {%1, %2, %3, %4};"
                 :: "l"(dst), "f"(r.x), "f"(r.y), "f"(r.z), "f"(r.w)
                 : "memory");
#else
    atomicAdd(dst + 0, r.x); atomicAdd(dst + 1, r.y);
    atomicAdd(dst + 2, r.z); atomicAdd(dst + 3, r.w);
#endif
}

// ===========================================================================
// Init a contiguous float4 range of the dense region with the padding row.
// Range base is D4-aligned; TB % D4 == 0 -> column depends only on tid.
// ===========================================================================
__global__ void k_init_range(float4* __restrict__ val4,
                             const float4* __restrict__ pad4,
                             long long count4, int D4)
{
    long long base = (long long)blockIdx.x * (TB * IPT) + threadIdx.x;
    float4 pv = __ldg(&pad4[(int)threadIdx.x & (D4 - 1)]);
    #pragma unroll
    for (int k = 0; k < IPT; k++) {
        long long v = base + (long long)k * TB;
        if (v < count4) val4[v] = pv;
    }
}

// ===========================================================================
// Idx pattern kernel (independent of dense region).
// ===========================================================================
__global__ void k_idx(float* __restrict__ out, long long P, int sn)
{
    long long P4 = P >> 2;
    long long t = (long long)blockIdx.x * TB + threadIdx.x;
    if (t >= P4) return;
    long long q = t << 2;
    int nm1  = (1 << sn) - 1;
    long long nnm1 = ((long long)1 << (2 * sn)) - 1;
    int b   = (int)(q >> (2 * sn));
    int rem = (int)(q & nnm1);
    int i   = rem >> sn;
    int j   = rem & nm1;
    float rv = (float)((b << sn) + i);
    float cv = (float)((b << sn) + j);
    ((float4*)out)[t]       = make_float4(rv, rv, rv, rv);
    ((float4*)(out + P))[t] = make_float4(cv, cv + 1.f, cv + 2.f, cv + 3.f);
}

// ===========================================================================
// Scatter a contiguous edge range [eLo, eLo+eCount) (R4-proven body).
// ===========================================================================
__global__ void k_scatter_range(const int* __restrict__ ei,
                                const float* __restrict__ pestat,
                                const float4* __restrict__ ea4,
                                const float4* __restrict__ w4,
                                float* __restrict__ val,
                                int E, int K, int s4, int sn,
                                int eLo, int eCount)
{
    int t = blockIdx.x * TB + threadIdx.x;
    if (t >= (eCount << s4)) return;
    int e = eLo + (t >> s4);
    int c = t & ((1 << s4) - 1);

    int u  = __ldg(&ei[e]);
    int rv = __ldg(&ei[E + e]) & ((1 << sn) - 1);

    float  p = __ldg(&pestat[(long long)e * K]);
    float4 a = __ldg(&ea4[((long long)e << s4) + c]);
    float4 w = __ldg(&w4[c]);
    float4 rr = make_float4(a.x + p * w.x, a.y + p * w.y,
                            a.z + p * w.z, a.w + p * w.w);

    long long slot = ((long long)u << sn) | rv;
    red_add_v4(val + (slot << (s4 + 2)) + (c << 2), rr);
}

// ===========================================================================
// Tier 2: proven serial path (R10): init + fused idx/scatter.
// ===========================================================================
__global__ void k_idx_scatter(float* __restrict__ out, long long P,
                              const int* __restrict__ ei,
                              const float* __restrict__ pestat,
                              const float4* __restrict__ ea4,
                              const float4* __restrict__ w4,
                              float* __restrict__ val,
                              int E, int K, int s4, int sn,
                              int idxBlocks)
{
    const int tid = threadIdx.x;
    const int bid = blockIdx.x;

    if (bid < idxBlocks) {
        long long P4 = P >> 2;
        long long t = (long long)bid * TB + tid;
        if (t >= P4) return;
        long long q = t << 2;
        int nm1  = (1 << sn) - 1;
        long long nnm1 = ((long long)1 << (2 * sn)) - 1;
        int b   = (int)(q >> (2 * sn));
        int rem = (int)(q & nnm1);
        int i   = rem >> sn;
        int j   = rem & nm1;
        float rv = (float)((b << sn) + i);
        float cv = (float)((b << sn) + j);
        ((float4*)out)[t]       = make_float4(rv, rv, rv, rv);
        ((float4*)(out + P))[t] = make_float4(cv, cv + 1.f, cv + 2.f, cv + 3.f);
        return;
    }

    int t = (bid - idxBlocks) * TB + tid;
    if (t >= (E << s4)) return;
    int e = t >> s4;
    int c = t & ((1 << s4) - 1);

    int u  = __ldg(&ei[e]);
    int rv = __ldg(&ei[E + e]) & ((1 << sn) - 1);
    float  p = __ldg(&pestat[(long long)e * K]);
    float4 a = __ldg(&ea4[((long long)e << s4) + c]);
    float4 w = __ldg(&w4[c]);
    float4 rr = make_float4(a.x + p * w.x, a.y + p * w.y,
                            a.z + p * w.z, a.w + p * w.w);
    long long slot = ((long long)u << sn) | rv;
    red_add_v4(val + (slot << (s4 + 2)) + (c << 2), rr);
}

// ===========================================================================
// Tier 3: fully generic fallbacks.
// ===========================================================================
__global__ void k_init_fused_s(float* __restrict__ out, const float* __restrict__ pad,
                               long long P, int n, int D)
{
    long long totalI = P;
    long long tot = P + P * (long long)D;
    float* val = out + 2 * P;
    long long stride = (long long)gridDim.x * blockDim.x;
    for (long long t = (long long)blockIdx.x * blockDim.x + threadIdx.x;
         t < tot; t += stride) {
        if (t < totalI) {
            long long nn = (long long)n * n;
            int b   = (int)(t / nn);
            int rem = (int)(t - (long long)b * nn);
            int i   = rem / n;
            int j   = rem - i * n;
            out[t]     = (float)(b * n + i);
            out[P + t] = (float)(b * n + j);
        } else {
            long long v = t - totalI;
            val[v] = __ldg(&pad[(int)(v % D)]);
        }
    }
}

__global__ void k_scatter_s(const int* __restrict__ ei, const float* __restrict__ pestat,
                            const float* __restrict__ ea, const float* __restrict__ w,
                            float* __restrict__ val, int E, int K, int D, int n)
{
    long long tot = (long long)E * D;
    long long stride = (long long)gridDim.x * blockDim.x;
    for (long long t = (long long)blockIdx.x * blockDim.x + threadIdx.x;
         t < tot; t += stride) {
        int e = (int)(t / D);
        int d = (int)(t - (long long)e * D);
        int u = __ldg(&ei[e]);
        int v = __ldg(&ei[E + e]);
        int g  = u / n;
        int ru = u - g * n;
        int rv = v % n;
        float p = __ldg(&pestat[(long long)e * K]);
        float x = ea[(long long)e * D + d] + p * __ldg(&w[d]);
        long long base = (((long long)g * n + ru) * n + rv) * (long long)D + d;
        atomicAdd(val + base, x);
    }
}

// ===========================================================================

static inline bool is_pow2(int x) { return x > 0 && (x & (x - 1)) == 0; }
static inline int  ilog2(int x)   { int s = 0; while ((1 << s) < x) s++; return s; }
static inline int grid_for(long long work, int tb)
{
    long long g = (work + tb - 1) / tb;
    if (g > 1048576) g = 1048576;
    if (g < 1) g = 1;
    return (int)g;
}

extern "C" void kernel_launch(void* const* d_in, const int* in_sizes, int n_in,
                              void* d_out, int out_size)
{
    // metadata order: edge_index, pestat, edge_attr, batch, fc_w, padding
    const int*   ei     = (const int*)  d_in[0];
    const float* pestat = (const float*)d_in[1];
    const float* ea     = (const float*)d_in[2];
    const float* fc_w   = (const float*)d_in[4];
    const float* pad    = (const float*)d_in[5];

    const int E = in_sizes[0] / 2;
    const int K = in_sizes[1] / E;
    const int D = in_sizes[2] / E;
    const int N = in_sizes[3];                            // dense rows = B*n
    const long long P = (long long)out_size / (D + 2);    // slots = B*n*n
    const int n = (int)(P / N);
    const int B = (n > 0) ? N / n : 0;

    float* out = (float*)d_out;
    float* val = out + 2 * P;
    const int D4 = D / 4;

    const bool pow2ok = (D % 4 == 0) && (n % 4 == 0) &&
                        is_pow2(n) && is_pow2(D4) && D4 <= 256 &&
                        ((long long)E * D4 < (1LL << 30));

    // Lazy one-time stream/event setup. First call is the uncaptured
    // correctness run, so creation never happens during graph capture.
    static cudaStream_t s2 = nullptr;
    static cudaEvent_t evFork = nullptr;
    static cudaEvent_t evInit[NCHUNK];
    static cudaEvent_t evJoin = nullptr;
    static bool streamsOk = false;
    static bool streamsTried = false;
    if (!streamsTried) {
        streamsTried = true;
        bool ok = (cudaStreamCreateWithFlags(&s2, cudaStreamNonBlocking) == cudaSuccess);
        if (ok) ok = (cudaEventCreateWithFlags(&evFork, cudaEventDisableTiming) == cudaSuccess);
        for (int i = 0; ok && i < NCHUNK; i++)
            ok = (cudaEventCreateWithFlags(&evInit[i], cudaEventDisableTiming) == cudaSuccess);
        if (ok) ok = (cudaEventCreateWithFlags(&evJoin, cudaEventDisableTiming) == cudaSuccess);
        streamsOk = ok;
    }

    const bool chunkok = pow2ok && streamsOk &&
                         (B >= NCHUNK) && (B % NCHUNK == 0) &&
                         (E % B == 0) && ((long long)N * n == P);

    if (chunkok) {
        const int sn = ilog2(n);
        const int s4 = ilog2(D4);
        const int epg = E / B;                            // edges per graph
        const int gPerChunk = B / NCHUNK;
        const long long perRow4   = (long long)n * D4;    // float4s per dense row
        const long long perChunk4 = (long long)gPerChunk * n * perRow4;

        // FORK: side stream must join the capture BEFORE launching anything.
        cudaEventRecord(evFork, 0);
        cudaStreamWaitEvent(s2, evFork, 0);

        // Side stream: idx pattern (independent of dense region).
        {
            int idxBlocks = (int)(((P >> 2) + TB - 1) / TB);
            k_idx<<<idxBlocks, TB, 0, s2>>>(out, P, sn);
        }

        // Origin stream: init chunks. Side stream: scatter chunk i after
        // init chunk i completes (event-gated) -> overlaps init chunk i+1.
        for (int i = 0; i < NCHUNK; i++) {
            float4* base4 = ((float4*)val) + (long long)i * perChunk4;
            int initBlocks = (int)((perChunk4 + (long long)TB * IPT - 1) /
                                   ((long long)TB * IPT));
            k_init_range<<<initBlocks, TB>>>(base4, (const float4*)pad,
                                             perChunk4, D4);
            cudaEventRecord(evInit[i], 0);

            cudaStreamWaitEvent(s2, evInit[i], 0);
            int eLo = i * gPerChunk * epg;
            int eCount = gPerChunk * epg;
            int scatBlocks = ((eCount << s4) + TB - 1) / TB;
            k_scatter_range<<<scatBlocks, TB, 0, s2>>>(ei, pestat,
                                                       (const float4*)ea,
                                                       (const float4*)fc_w,
                                                       val, E, K, s4, sn,
                                                       eLo, eCount);
        }

        // JOIN: origin stream waits for the side stream's last work.
        cudaEventRecord(evJoin, s2);
        cudaStreamWaitEvent(0, evJoin, 0);
    } else if (pow2ok) {
        const int sn = ilog2(n);
        const int s4 = ilog2(D4);
        const long long V4 = P * (long long)D4;

        long long initBlocks = (V4 + (long long)TB * IPT - 1) / ((long long)TB * IPT);
        k_init_range<<<(int)initBlocks, TB>>>((float4*)val, (const float4*)pad,
                                              V4, D4);

        const int idxBlocks  = (int)(((P >> 2) + TB - 1) / TB);
        const int scatBlocks = (int)(((long long)(E << s4) + TB - 1) / TB);
        k_idx_scatter<<<idxBlocks + scatBlocks, TB>>>(out, P, ei, pestat,
                                                      (const float4*)ea,
                                                      (const float4*)fc_w,
                                                      val, E, K, s4, sn,
                                                      idxBlocks);
    } else {
        long long tot = P + P * (long long)D;
        k_init_fused_s<<<grid_for(tot, TB), TB>>>(out, pad, P, n, D);
        long long st = (long long)E * D;
        k_scatter_s<<<grid_for(st, TB), TB>>>(ei, pestat, ea, fc_w, val,
                                              E, K, D, n);
    }
}